// round 14
// baseline (speedup 1.0000x reference)
#include <cuda_runtime.h>

// GNNPolicy: 2-layer GCN + node logits head + graph mean-pool value head.
// CSR-gather aggregation (MLP-4 unrolled), smem-staged GEMMs with f32x2 FMA,
// stream-forked GEMM1 || CSR build, gather1+GEMM2 fused, gather2+heads+value fused.
// Inputs: x[N,128] f32, edge_index[2,E] int32, batch[N] int32,
//   W1[128,64], b1[64], W2[64,64], b2[64], Wa[64,1], ba[1], Wc[64,1], bc[1]
// Output: concat(action_logits[N], value[G]) as float32, out_size = N + G.

#define HD 64
#define MAXN 100000
#define MAXE 1600000
#define MAXG 64
#define SCB  1024   // scan block width

typedef unsigned long long u64;

// ---- scratch ----
__device__ __align__(16) int   g_cnt[MAXN];
__device__ __align__(16) int   g_rowptr[MAXN];
__device__ __align__(16) int   g_cursor[MAXN];
__device__ __align__(16) int   g_csrc[MAXE];
__device__ __align__(16) int   g_bsum[256];
__device__ __align__(16) float g_dinv[MAXN];
__device__ __align__(16) float g_T[(size_t)MAXN * HD];    // layer1: raw X@W1
__device__ __align__(16) float g_T2[(size_t)MAXN * HD];   // layer2: premult dinv
__device__ __align__(16) float g_pooled[MAXG * HD];
__device__ __align__(16) float g_counts[MAXG];
__device__ unsigned g_done;

// ---- packed f32x2 helpers ----
__device__ __forceinline__ u64 pk2(float a, float b) {
    u64 r; asm("mov.b64 %0, {%1, %2};" : "=l"(r) : "f"(a), "f"(b)); return r;
}
__device__ __forceinline__ void fma2(u64& d, u64 a, u64 b) {
    asm("fma.rn.f32x2 %0, %1, %2, %0;" : "+l"(d) : "l"(a), "l"(b));
}
__device__ __forceinline__ float hsum2(u64 v) {
    float x, y; asm("mov.b64 {%0, %1}, %2;" : "=f"(x), "=f"(y) : "l"(v)); return x + y;
}

__device__ __forceinline__ void atomic_add_v4(float4* addr, float4 v) {
#if defined(__CUDA_ARCH__) && (__CUDA_ARCH__ >= 900)
    atomicAdd(addr, v);
#else
    float* a = (float*)addr;
    atomicAdd(a + 0, v.x); atomicAdd(a + 1, v.y);
    atomicAdd(a + 2, v.z); atomicAdd(a + 3, v.w);
#endif
}

// ---- zero ----
__global__ void k_zero(int n) {
    int i = blockIdx.x * blockDim.x + threadIdx.x;
    if (i < n) g_cnt[i] = 0;
    if (i < MAXG * HD) g_pooled[i] = 0.0f;
    if (i < MAXG) g_counts[i] = 0.0f;
    if (i == 0) g_done = 0u;
}

// ---- histogram over dst ----
__global__ void k_hist(const int* __restrict__ ei, int E, int n) {
    int e = blockIdx.x * blockDim.x + threadIdx.x;
    if (e < E) {
        int dst = ei[E + e];
        if ((unsigned)dst < (unsigned)n) atomicAdd(&g_cnt[dst], 1);
    }
}

// ---- scan level 1: per-block exclusive scan of cnt, publish block sums ----
__global__ void k_scan1(int n) {
    __shared__ int s[SCB];
    int t = threadIdx.x;
    int i = blockIdx.x * SCB + t;
    int v = (i < n) ? g_cnt[i] : 0;
    s[t] = v;
    __syncthreads();
#pragma unroll
    for (int off = 1; off < SCB; off <<= 1) {
        int x = (t >= off) ? s[t - off] : 0;
        __syncthreads();
        s[t] += x;
        __syncthreads();
    }
    if (i < n) g_rowptr[i] = s[t] - v;
    if (t == SCB - 1) g_bsum[blockIdx.x] = s[t];
}

// ---- scanB: each block redundantly scans block-sums (<=256), applies offsets,
// inits cursors and dinv. Replaces scan2+scan3.
__global__ void k_scanB(int n, int nb) {
    __shared__ int s[256];
    __shared__ int off[256];
    int t = threadIdx.x;
    int v = (t < nb) ? g_bsum[t] : 0;
    s[t] = v;
    __syncthreads();
#pragma unroll
    for (int o = 1; o < 256; o <<= 1) {
        int x = (t >= o) ? s[t - o] : 0;
        __syncthreads();
        s[t] += x;
        __syncthreads();
    }
    off[t] = s[t] - v;          // exclusive block offset
    __syncthreads();
    int i = blockIdx.x * 256 + t;
    if (i < n) {
        int rp = g_rowptr[i] + off[i >> 10];
        g_rowptr[i] = rp;
        g_cursor[i] = rp;
        g_dinv[i]   = rsqrtf((float)(g_cnt[i] + 1));
    }
}

// ---- fill CSR ----
__global__ void k_fill(const int* __restrict__ ei, int E, int n) {
    int e = blockIdx.x * blockDim.x + threadIdx.x;
    if (e < E) {
        int src = ei[e];
        int dst = ei[E + e];
        if ((unsigned)src < (unsigned)n && (unsigned)dst < (unsigned)n) {
            int pos = atomicAdd(&g_cursor[dst], 1);
            g_csrc[pos] = src;
        }
    }
}

// ---- GEMM1: T = X @ W1 (raw; concurrent with CSR build) ----
__global__ void k_gemm1(const float* __restrict__ X, const float* __restrict__ W,
                        int n) {
    const int K = 128;
    extern __shared__ __align__(16) float sm[];
    float* Wt = sm;                       // [64][132]
    float* Xs = sm + HD * (K + 4);        // [64][132]
    const int NF4 = K / 4;

    int tid = threadIdx.x;
    int row0 = blockIdx.x * 64;

    for (int idx = tid; idx < K * HD; idx += 256) {
        int k = idx >> 6, c = idx & 63;
        Wt[c * (K + 4) + k] = W[idx];
    }
    for (int i = tid; i < 64 * NF4; i += 256) {
        int r = i / NF4, c = i % NF4;
        int rr = row0 + r;
        float4 v = make_float4(0.f, 0.f, 0.f, 0.f);
        if (rr < n) v = ((const float4*)X)[(size_t)rr * NF4 + c];
        *(float4*)&Xs[r * (K + 4) + c * 4] = v;
    }
    __syncthreads();

    int warp = tid >> 5, lane = tid & 31;
    const float* wt0 = &Wt[lane * (K + 4)];
    const float* wt1 = &Wt[(lane + 32) * (K + 4)];
    const float* xr0 = &Xs[(warp * 8) * (K + 4)];

    u64 acc0[8], acc1[8];
#pragma unroll
    for (int r = 0; r < 8; r++) { acc0[r] = 0ull; acc1[r] = 0ull; }

#pragma unroll 4
    for (int k = 0; k < K; k += 4) {
        float4 wa = *(const float4*)(wt0 + k);
        float4 wb = *(const float4*)(wt1 + k);
        u64 wa01 = pk2(wa.x, wa.y), wa23 = pk2(wa.z, wa.w);
        u64 wb01 = pk2(wb.x, wb.y), wb23 = pk2(wb.z, wb.w);
#pragma unroll
        for (int r = 0; r < 8; r++) {
            float4 xv = *(const float4*)(xr0 + r * (K + 4) + k);
            u64 x01 = pk2(xv.x, xv.y), x23 = pk2(xv.z, xv.w);
            fma2(acc0[r], x01, wa01); fma2(acc0[r], x23, wa23);
            fma2(acc1[r], x01, wb01); fma2(acc1[r], x23, wb23);
        }
    }

    int rbase = row0 + warp * 8;
#pragma unroll
    for (int r = 0; r < 8; r++) {
        int rr = rbase + r;
        if (rr < n) {
            g_T[(size_t)rr * HD + lane]      = hsum2(acc0[r]);
            g_T[(size_t)rr * HD + lane + 32] = hsum2(acc1[r]);
        }
    }
}

// ---- fused gather1 + GEMM2 (agg1 in smem only); MLP-4 gather loop ----
__global__ void k_fuse1(const float* __restrict__ W2, const float* __restrict__ b1,
                        int n) {
    const int K = 64;
    extern __shared__ __align__(16) float sm[];
    float* Wt = sm;                       // [64][68]
    float* Xs = sm + HD * (K + 4);        // [64][68]

    int tid = threadIdx.x;
    int row0 = blockIdx.x * 64;

    for (int idx = tid; idx < K * HD; idx += 256) {
        int k = idx >> 6, c = idx & 63;
        Wt[c * (K + 4) + k] = W2[idx];
    }

    int l = tid & 15;
    float4 bb = ((const float4*)b1)[l];
#pragma unroll
    for (int it = 0; it < 4; it++) {
        int r = it * 16 + (tid >> 4);
        int v = row0 + r;
        float4 s0 = make_float4(0.f, 0.f, 0.f, 0.f);
        if (v < n) {
            float dv = g_dinv[v];
            float4 t = ((const float4*)(g_T + (size_t)v * HD))[l];
            s0.x = t.x * dv; s0.y = t.y * dv; s0.z = t.z * dv; s0.w = t.w * dv;
            int start = g_rowptr[v];
            int cnt   = g_cnt[v];
            float4 s1 = make_float4(0.f,0.f,0.f,0.f);
            float4 s2 = make_float4(0.f,0.f,0.f,0.f);
            float4 s3 = make_float4(0.f,0.f,0.f,0.f);
            int j = 0;
            for (; j + 4 <= cnt; j += 4) {          // 4 independent loads in flight
                int u0 = g_csrc[start + j];
                int u1 = g_csrc[start + j + 1];
                int u2 = g_csrc[start + j + 2];
                int u3 = g_csrc[start + j + 3];
                float d0 = g_dinv[u0], d1 = g_dinv[u1];
                float d2 = g_dinv[u2], d3 = g_dinv[u3];
                float4 a = ((const float4*)(g_T + (size_t)u0 * HD))[l];
                float4 b = ((const float4*)(g_T + (size_t)u1 * HD))[l];
                float4 c = ((const float4*)(g_T + (size_t)u2 * HD))[l];
                float4 d = ((const float4*)(g_T + (size_t)u3 * HD))[l];
                s0.x += a.x*d0; s0.y += a.y*d0; s0.z += a.z*d0; s0.w += a.w*d0;
                s1.x += b.x*d1; s1.y += b.y*d1; s1.z += b.z*d1; s1.w += b.w*d1;
                s2.x += c.x*d2; s2.y += c.y*d2; s2.z += c.z*d2; s2.w += c.w*d2;
                s3.x += d.x*d3; s3.y += d.y*d3; s3.z += d.z*d3; s3.w += d.w*d3;
            }
            for (; j < cnt; j++) {
                int u = g_csrc[start + j];
                float du = g_dinv[u];
                float4 tu = ((const float4*)(g_T + (size_t)u * HD))[l];
                s0.x += tu.x*du; s0.y += tu.y*du; s0.z += tu.z*du; s0.w += tu.w*du;
            }
            s0.x += s1.x + s2.x + s3.x; s0.y += s1.y + s2.y + s3.y;
            s0.z += s1.z + s2.z + s3.z; s0.w += s1.w + s2.w + s3.w;
            s0.x = fmaxf(dv * s0.x + bb.x, 0.0f);
            s0.y = fmaxf(dv * s0.y + bb.y, 0.0f);
            s0.z = fmaxf(dv * s0.z + bb.z, 0.0f);
            s0.w = fmaxf(dv * s0.w + bb.w, 0.0f);
        }
        *(float4*)&Xs[r * (K + 4) + l * 4] = s0;
    }
    __syncthreads();

    int warp = tid >> 5, lane = tid & 31;
    const float* wt0 = &Wt[lane * (K + 4)];
    const float* wt1 = &Wt[(lane + 32) * (K + 4)];
    const float* xr0 = &Xs[(warp * 8) * (K + 4)];

    u64 acc0[8], acc1[8];
#pragma unroll
    for (int r = 0; r < 8; r++) { acc0[r] = 0ull; acc1[r] = 0ull; }

#pragma unroll 4
    for (int k = 0; k < K; k += 4) {
        float4 wa = *(const float4*)(wt0 + k);
        float4 wb = *(const float4*)(wt1 + k);
        u64 wa01 = pk2(wa.x, wa.y), wa23 = pk2(wa.z, wa.w);
        u64 wb01 = pk2(wb.x, wb.y), wb23 = pk2(wb.z, wb.w);
#pragma unroll
        for (int r = 0; r < 8; r++) {
            float4 xv = *(const float4*)(xr0 + r * (K + 4) + k);
            u64 x01 = pk2(xv.x, xv.y), x23 = pk2(xv.z, xv.w);
            fma2(acc0[r], x01, wa01); fma2(acc0[r], x23, wa23);
            fma2(acc1[r], x01, wb01); fma2(acc1[r], x23, wb23);
        }
    }

    int rbase = row0 + warp * 8;
#pragma unroll
    for (int r = 0; r < 8; r++) {
        int rr = rbase + r;
        if (rr < n) {
            float di = g_dinv[rr];
            g_T2[(size_t)rr * HD + lane]      = hsum2(acc0[r]) * di;
            g_T2[(size_t)rr * HD + lane + 32] = hsum2(acc1[r]) * di;
        }
    }
}

// ---- fused gather2 + heads + value (last block) ----
__global__ void k_fuse2(const float* __restrict__ b2, const int* __restrict__ batch,
                        const float* __restrict__ Wa, const float* __restrict__ ba,
                        const float* __restrict__ Wc, const float* __restrict__ bc,
                        float* __restrict__ out, int n, int G) {
    int tid = blockIdx.x * blockDim.x + threadIdx.x;
    int v = tid >> 4;
    int l = tid & 15;
    if (v < n) {
        int start = g_rowptr[v];
        int cnt   = g_cnt[v];
        float4 s0 = ((const float4*)(g_T2 + (size_t)v * HD))[l];  // self (premult)
        float4 s1 = make_float4(0.f,0.f,0.f,0.f);
        float4 s2 = make_float4(0.f,0.f,0.f,0.f);
        float4 s3 = make_float4(0.f,0.f,0.f,0.f);
        int j = 0;
        for (; j + 4 <= cnt; j += 4) {
            int u0 = g_csrc[start + j];
            int u1 = g_csrc[start + j + 1];
            int u2 = g_csrc[start + j + 2];
            int u3 = g_csrc[start + j + 3];
            float4 a = ((const float4*)(g_T2 + (size_t)u0 * HD))[l];
            float4 b = ((const float4*)(g_T2 + (size_t)u1 * HD))[l];
            float4 c = ((const float4*)(g_T2 + (size_t)u2 * HD))[l];
            float4 d = ((const float4*)(g_T2 + (size_t)u3 * HD))[l];
            s0.x += a.x; s0.y += a.y; s0.z += a.z; s0.w += a.w;
            s1.x += b.x; s1.y += b.y; s1.z += b.z; s1.w += b.w;
            s2.x += c.x; s2.y += c.y; s2.z += c.z; s2.w += c.w;
            s3.x += d.x; s3.y += d.y; s3.z += d.z; s3.w += d.w;
        }
        for (; j < cnt; j++) {
            int u = g_csrc[start + j];
            float4 t = ((const float4*)(g_T2 + (size_t)u * HD))[l];
            s0.x += t.x; s0.y += t.y; s0.z += t.z; s0.w += t.w;
        }
        s0.x += s1.x + s2.x + s3.x; s0.y += s1.y + s2.y + s3.y;
        s0.z += s1.z + s2.z + s3.z; s0.w += s1.w + s2.w + s3.w;

        float dv = g_dinv[v];
        float4 bb = ((const float4*)b2)[l];
        float4 h;
        h.x = fmaxf(bb.x + dv * s0.x, 0.0f);
        h.y = fmaxf(bb.y + dv * s0.y, 0.0f);
        h.z = fmaxf(bb.z + dv * s0.z, 0.0f);
        h.w = fmaxf(bb.w + dv * s0.w, 0.0f);

        float4 wa = ((const float4*)Wa)[l];
        float sl = h.x * wa.x + h.y * wa.y + h.z * wa.z + h.w * wa.w;
        sl += __shfl_xor_sync(0xffffffffu, sl, 8);
        sl += __shfl_xor_sync(0xffffffffu, sl, 4);
        sl += __shfl_xor_sync(0xffffffffu, sl, 2);
        sl += __shfl_xor_sync(0xffffffffu, sl, 1);

        int g = batch[v];
        if ((unsigned)g < (unsigned)MAXG) {
            atomic_add_v4((float4*)(g_pooled + g * HD) + l, h);
            if (l == 0) atomicAdd(&g_counts[g], 1.0f);
        }
        if (l == 0) out[v] = sl + ba[0];
    }

    // ---- completion counter: last block computes the value head ----
    __shared__ unsigned s_ticket;
    __threadfence();
    __syncthreads();
    if (threadIdx.x == 0) s_ticket = atomicAdd(&g_done, 1u);
    __syncthreads();
    if (s_ticket == (unsigned)(gridDim.x - 1)) {
        int lane = threadIdx.x & 31, w = threadIdx.x >> 5;
        for (int g = w; g < G; g += 8) {
            float s = g_pooled[g * HD + lane] * Wc[lane]
                    + g_pooled[g * HD + 32 + lane] * Wc[32 + lane];
            s += __shfl_xor_sync(0xffffffffu, s, 16);
            s += __shfl_xor_sync(0xffffffffu, s, 8);
            s += __shfl_xor_sync(0xffffffffu, s, 4);
            s += __shfl_xor_sync(0xffffffffu, s, 2);
            s += __shfl_xor_sync(0xffffffffu, s, 1);
            if (lane == 0)
                out[n + g] = s / fmaxf(g_counts[g], 1.0f) + bc[0];
        }
    }
}

extern "C" void kernel_launch(void* const* d_in, const int* in_sizes, int n_in,
                              void* d_out, int out_size) {
    const float* x     = (const float*)d_in[0];
    const int*   ei    = (const int*)d_in[1];      // int32 (JAX x64 disabled)
    const int*   batch = (const int*)d_in[2];      // int32
    const float* W1    = (const float*)d_in[3];
    const float* b1    = (const float*)d_in[4];
    const float* W2    = (const float*)d_in[5];
    const float* b2    = (const float*)d_in[6];
    const float* Wa    = (const float*)d_in[7];
    const float* ba    = (const float*)d_in[8];
    const float* Wc    = (const float*)d_in[9];
    const float* bc    = (const float*)d_in[10];
    float* out = (float*)d_out;

    int n = in_sizes[2];
    int E = in_sizes[1] / 2;
    int G = out_size - n;   // = 64
    int nb = (n + SCB - 1) / SCB;

    int smem1 = 2 * HD * (128 + 4) * sizeof(float);   // 67584 (GEMM1)
    int smemF = 2 * HD * (64 + 4) * sizeof(float);    // 34816 (fuse1)
    cudaFuncSetAttribute(k_gemm1, cudaFuncAttributeMaxDynamicSharedMemorySize, smem1);
    cudaFuncSetAttribute(k_fuse1, cudaFuncAttributeMaxDynamicSharedMemorySize, smemF);

    // ---- fork: GEMM1 on side stream, CSR build on main stream ----
    cudaStream_t s1;
    cudaStreamCreateWithFlags(&s1, cudaStreamNonBlocking);
    cudaEvent_t ev_fork, ev_join;
    cudaEventCreateWithFlags(&ev_fork, cudaEventDisableTiming);
    cudaEventCreateWithFlags(&ev_join, cudaEventDisableTiming);

    cudaEventRecord(ev_fork, 0);
    cudaStreamWaitEvent(s1, ev_fork, 0);
    k_gemm1<<<(n + 63) / 64, 256, smem1, s1>>>(x, W1, n);
    cudaEventRecord(ev_join, s1);

    k_zero<<<(n + 255) / 256, 256>>>(n);
    k_hist<<<(E + 255) / 256, 256>>>(ei, E, n);
    k_scan1<<<nb, SCB>>>(n);
    k_scanB<<<(n + 255) / 256, 256>>>(n, nb);
    k_fill<<<(E + 255) / 256, 256>>>(ei, E, n);

    cudaStreamWaitEvent(0, ev_join, 0);   // join GEMM1

    k_fuse1<<<(n + 63) / 64, 256, smemF>>>(W2, b1, n);
    k_fuse2<<<(n * 16 + 255) / 256, 256>>>(b2, batch, Wa, ba, Wc, bc, out, n, G);

    cudaEventDestroy(ev_fork);
    cudaEventDestroy(ev_join);
    cudaStreamDestroy(s1);
}

// round 15
// speedup vs baseline: 1.0690x; 1.0690x over previous
#include <cuda_runtime.h>

// GNNPolicy: 2-layer GCN + node logits head + graph mean-pool value head.
// CSR-gather aggregation, smem-staged GEMMs with f32x2 FMA, stream-forked
// GEMM1 || CSR build, gather1+GEMM2 fused, gather2+heads fused (MLP-4 gather).
// Inputs: x[N,128] f32, edge_index[2,E] int32, batch[N] int32,
//   W1[128,64], b1[64], W2[64,64], b2[64], Wa[64,1], ba[1], Wc[64,1], bc[1]
// Output: concat(action_logits[N], value[G]) as float32, out_size = N + G.

#define HD 64
#define MAXN 100000
#define MAXE 1600000
#define MAXG 64
#define SCB  1024   // scan block width

typedef unsigned long long u64;

// ---- scratch ----
__device__ __align__(16) int   g_cnt[MAXN];
__device__ __align__(16) int   g_rowptr[MAXN];
__device__ __align__(16) int   g_cursor[MAXN];
__device__ __align__(16) int   g_csrc[MAXE];
__device__ __align__(16) int   g_bsum[256];
__device__ __align__(16) float g_dinv[MAXN];
__device__ __align__(16) float g_T[(size_t)MAXN * HD];    // layer1: raw X@W1
__device__ __align__(16) float g_T2[(size_t)MAXN * HD];   // layer2: premult dinv
__device__ __align__(16) float g_pooled[MAXG * HD];
__device__ __align__(16) float g_counts[MAXG];

// ---- packed f32x2 helpers ----
__device__ __forceinline__ u64 pk2(float a, float b) {
    u64 r; asm("mov.b64 %0, {%1, %2};" : "=l"(r) : "f"(a), "f"(b)); return r;
}
__device__ __forceinline__ void fma2(u64& d, u64 a, u64 b) {
    asm("fma.rn.f32x2 %0, %1, %2, %0;" : "+l"(d) : "l"(a), "l"(b));
}
__device__ __forceinline__ float hsum2(u64 v) {
    float x, y; asm("mov.b64 {%0, %1}, %2;" : "=f"(x), "=f"(y) : "l"(v)); return x + y;
}

__device__ __forceinline__ void atomic_add_v4(float4* addr, float4 v) {
#if defined(__CUDA_ARCH__) && (__CUDA_ARCH__ >= 900)
    atomicAdd(addr, v);
#else
    float* a = (float*)addr;
    atomicAdd(a + 0, v.x); atomicAdd(a + 1, v.y);
    atomicAdd(a + 2, v.z); atomicAdd(a + 3, v.w);
#endif
}

// ---- zero ----
__global__ void k_zero(int n) {
    int i = blockIdx.x * blockDim.x + threadIdx.x;
    if (i < n) g_cnt[i] = 0;
    if (i < MAXG * HD) g_pooled[i] = 0.0f;
    if (i < MAXG) g_counts[i] = 0.0f;
}

// ---- histogram over dst ----
__global__ void k_hist(const int* __restrict__ ei, int E, int n) {
    int e = blockIdx.x * blockDim.x + threadIdx.x;
    if (e < E) {
        int dst = ei[E + e];
        if ((unsigned)dst < (unsigned)n) atomicAdd(&g_cnt[dst], 1);
    }
}

// ---- scan level 1: per-block exclusive scan of cnt, publish block sums ----
__global__ void k_scan1(int n) {
    __shared__ int s[SCB];
    int t = threadIdx.x;
    int i = blockIdx.x * SCB + t;
    int v = (i < n) ? g_cnt[i] : 0;
    s[t] = v;
    __syncthreads();
#pragma unroll
    for (int off = 1; off < SCB; off <<= 1) {
        int x = (t >= off) ? s[t - off] : 0;
        __syncthreads();
        s[t] += x;
        __syncthreads();
    }
    if (i < n) g_rowptr[i] = s[t] - v;
    if (t == SCB - 1) g_bsum[blockIdx.x] = s[t];
}

// ---- scanB: each block redundantly scans block-sums (<=256 entries) in smem,
// applies offsets, inits cursors + dinv. Replaces scan2+scan3 (one launch less).
__global__ void k_scanB(int n, int nb) {
    __shared__ int s[256];
    __shared__ int off[256];
    int t = threadIdx.x;
    int v = (t < nb) ? g_bsum[t] : 0;
    s[t] = v;
    __syncthreads();
#pragma unroll
    for (int o = 1; o < 256; o <<= 1) {
        int x = (t >= o) ? s[t - o] : 0;
        __syncthreads();
        s[t] += x;
        __syncthreads();
    }
    off[t] = s[t] - v;          // exclusive block offset
    __syncthreads();
    int i = blockIdx.x * 256 + t;
    if (i < n) {
        int rp = g_rowptr[i] + off[i >> 10];
        g_rowptr[i] = rp;
        g_cursor[i] = rp;
        g_dinv[i]   = rsqrtf((float)(g_cnt[i] + 1));
    }
}

// ---- fill CSR ----
__global__ void k_fill(const int* __restrict__ ei, int E, int n) {
    int e = blockIdx.x * blockDim.x + threadIdx.x;
    if (e < E) {
        int src = ei[e];
        int dst = ei[E + e];
        if ((unsigned)src < (unsigned)n && (unsigned)dst < (unsigned)n) {
            int pos = atomicAdd(&g_cursor[dst], 1);
            g_csrc[pos] = src;
        }
    }
}

// ---- GEMM1: T = X @ W1 (raw; concurrent with CSR build) ----
__global__ void k_gemm1(const float* __restrict__ X, const float* __restrict__ W,
                        int n) {
    const int K = 128;
    extern __shared__ __align__(16) float sm[];
    float* Wt = sm;                       // [64][132]
    float* Xs = sm + HD * (K + 4);        // [64][132]
    const int NF4 = K / 4;

    int tid = threadIdx.x;
    int row0 = blockIdx.x * 64;

    for (int idx = tid; idx < K * HD; idx += 256) {
        int k = idx >> 6, c = idx & 63;
        Wt[c * (K + 4) + k] = W[idx];
    }
    for (int i = tid; i < 64 * NF4; i += 256) {
        int r = i / NF4, c = i % NF4;
        int rr = row0 + r;
        float4 v = make_float4(0.f, 0.f, 0.f, 0.f);
        if (rr < n) v = ((const float4*)X)[(size_t)rr * NF4 + c];
        *(float4*)&Xs[r * (K + 4) + c * 4] = v;
    }
    __syncthreads();

    int warp = tid >> 5, lane = tid & 31;
    const float* wt0 = &Wt[lane * (K + 4)];
    const float* wt1 = &Wt[(lane + 32) * (K + 4)];
    const float* xr0 = &Xs[(warp * 8) * (K + 4)];

    u64 acc0[8], acc1[8];
#pragma unroll
    for (int r = 0; r < 8; r++) { acc0[r] = 0ull; acc1[r] = 0ull; }

#pragma unroll 4
    for (int k = 0; k < K; k += 4) {
        float4 wa = *(const float4*)(wt0 + k);
        float4 wb = *(const float4*)(wt1 + k);
        u64 wa01 = pk2(wa.x, wa.y), wa23 = pk2(wa.z, wa.w);
        u64 wb01 = pk2(wb.x, wb.y), wb23 = pk2(wb.z, wb.w);
#pragma unroll
        for (int r = 0; r < 8; r++) {
            float4 xv = *(const float4*)(xr0 + r * (K + 4) + k);
            u64 x01 = pk2(xv.x, xv.y), x23 = pk2(xv.z, xv.w);
            fma2(acc0[r], x01, wa01); fma2(acc0[r], x23, wa23);
            fma2(acc1[r], x01, wb01); fma2(acc1[r], x23, wb23);
        }
    }

    int rbase = row0 + warp * 8;
#pragma unroll
    for (int r = 0; r < 8; r++) {
        int rr = rbase + r;
        if (rr < n) {
            g_T[(size_t)rr * HD + lane]      = hsum2(acc0[r]);
            g_T[(size_t)rr * HD + lane + 32] = hsum2(acc1[r]);
        }
    }
}

// ---- fused gather1 + GEMM2 (agg1 in smem only); serial-prefetch gather (R13) ----
__global__ void k_fuse1(const float* __restrict__ W2, const float* __restrict__ b1,
                        int n) {
    const int K = 64;
    extern __shared__ __align__(16) float sm[];
    float* Wt = sm;                       // [64][68]
    float* Xs = sm + HD * (K + 4);        // [64][68]

    int tid = threadIdx.x;
    int row0 = blockIdx.x * 64;

    for (int idx = tid; idx < K * HD; idx += 256) {
        int k = idx >> 6, c = idx & 63;
        Wt[c * (K + 4) + k] = W2[idx];
    }

    // gather phase: 16 lanes/node, 16 nodes in flight, 4 passes
    int l = tid & 15;
    float4 bb = ((const float4*)b1)[l];
#pragma unroll
    for (int it = 0; it < 4; it++) {
        int r = it * 16 + (tid >> 4);
        int v = row0 + r;
        float4 s = make_float4(0.f, 0.f, 0.f, 0.f);
        if (v < n) {
            float dv = g_dinv[v];
            float4 t = ((const float4*)(g_T + (size_t)v * HD))[l];
            s.x = t.x * dv; s.y = t.y * dv; s.z = t.z * dv; s.w = t.w * dv;
            int start = g_rowptr[v];
            int cnt   = g_cnt[v];
            int u = (cnt > 0) ? g_csrc[start] : 0;
            for (int j = 0; j < cnt; j++) {
                int un = (j + 1 < cnt) ? g_csrc[start + j + 1] : 0;
                float du = g_dinv[u];
                float4 tu = ((const float4*)(g_T + (size_t)u * HD))[l];
                s.x += tu.x * du; s.y += tu.y * du;
                s.z += tu.z * du; s.w += tu.w * du;
                u = un;
            }
            s.x = fmaxf(dv * s.x + bb.x, 0.0f);
            s.y = fmaxf(dv * s.y + bb.y, 0.0f);
            s.z = fmaxf(dv * s.z + bb.z, 0.0f);
            s.w = fmaxf(dv * s.w + bb.w, 0.0f);
        }
        *(float4*)&Xs[r * (K + 4) + l * 4] = s;
    }
    __syncthreads();

    // GEMM phase (packed f32x2)
    int warp = tid >> 5, lane = tid & 31;
    const float* wt0 = &Wt[lane * (K + 4)];
    const float* wt1 = &Wt[(lane + 32) * (K + 4)];
    const float* xr0 = &Xs[(warp * 8) * (K + 4)];

    u64 acc0[8], acc1[8];
#pragma unroll
    for (int r = 0; r < 8; r++) { acc0[r] = 0ull; acc1[r] = 0ull; }

#pragma unroll 4
    for (int k = 0; k < K; k += 4) {
        float4 wa = *(const float4*)(wt0 + k);
        float4 wb = *(const float4*)(wt1 + k);
        u64 wa01 = pk2(wa.x, wa.y), wa23 = pk2(wa.z, wa.w);
        u64 wb01 = pk2(wb.x, wb.y), wb23 = pk2(wb.z, wb.w);
#pragma unroll
        for (int r = 0; r < 8; r++) {
            float4 xv = *(const float4*)(xr0 + r * (K + 4) + k);
            u64 x01 = pk2(xv.x, xv.y), x23 = pk2(xv.z, xv.w);
            fma2(acc0[r], x01, wa01); fma2(acc0[r], x23, wa23);
            fma2(acc1[r], x01, wb01); fma2(acc1[r], x23, wb23);
        }
    }

    int rbase = row0 + warp * 8;
#pragma unroll
    for (int r = 0; r < 8; r++) {
        int rr = rbase + r;
        if (rr < n) {
            float di = g_dinv[rr];
            g_T2[(size_t)rr * HD + lane]      = hsum2(acc0[r]) * di;
            g_T2[(size_t)rr * HD + lane + 32] = hsum2(acc1[r]) * di;
        }
    }
}

// ---- fused gather2 + heads (MLP-4 gather; no GEMM phase -> regs are free) ----
__global__ void k_fuse2(const float* __restrict__ b2, const int* __restrict__ batch,
                        const float* __restrict__ Wa, const float* __restrict__ ba,
                        float* __restrict__ out, int n) {
    int tid = blockIdx.x * blockDim.x + threadIdx.x;
    int v = tid >> 4;
    if (v >= n) return;
    int l = tid & 15;
    int start = g_rowptr[v];
    int cnt   = g_cnt[v];
    float4 s0 = ((const float4*)(g_T2 + (size_t)v * HD))[l];  // self (premult)
    float4 s1 = make_float4(0.f,0.f,0.f,0.f);
    float4 s2 = make_float4(0.f,0.f,0.f,0.f);
    float4 s3 = make_float4(0.f,0.f,0.f,0.f);
    int j = 0;
    for (; j + 4 <= cnt; j += 4) {              // 4 independent row loads in flight
        int u0 = g_csrc[start + j];
        int u1 = g_csrc[start + j + 1];
        int u2 = g_csrc[start + j + 2];
        int u3 = g_csrc[start + j + 3];
        float4 a = ((const float4*)(g_T2 + (size_t)u0 * HD))[l];
        float4 b = ((const float4*)(g_T2 + (size_t)u1 * HD))[l];
        float4 c = ((const float4*)(g_T2 + (size_t)u2 * HD))[l];
        float4 d = ((const float4*)(g_T2 + (size_t)u3 * HD))[l];
        s0.x += a.x; s0.y += a.y; s0.z += a.z; s0.w += a.w;
        s1.x += b.x; s1.y += b.y; s1.z += b.z; s1.w += b.w;
        s2.x += c.x; s2.y += c.y; s2.z += c.z; s2.w += c.w;
        s3.x += d.x; s3.y += d.y; s3.z += d.z; s3.w += d.w;
    }
    for (; j < cnt; j++) {
        int u = g_csrc[start + j];
        float4 t = ((const float4*)(g_T2 + (size_t)u * HD))[l];
        s0.x += t.x; s0.y += t.y; s0.z += t.z; s0.w += t.w;
    }
    s0.x += s1.x + s2.x + s3.x; s0.y += s1.y + s2.y + s3.y;
    s0.z += s1.z + s2.z + s3.z; s0.w += s1.w + s2.w + s3.w;

    float dv = g_dinv[v];
    float4 bb = ((const float4*)b2)[l];
    float4 h;
    h.x = fmaxf(bb.x + dv * s0.x, 0.0f);
    h.y = fmaxf(bb.y + dv * s0.y, 0.0f);
    h.z = fmaxf(bb.z + dv * s0.z, 0.0f);
    h.w = fmaxf(bb.w + dv * s0.w, 0.0f);

    float4 wa = ((const float4*)Wa)[l];
    float sl = h.x * wa.x + h.y * wa.y + h.z * wa.z + h.w * wa.w;
    sl += __shfl_xor_sync(0xffffffffu, sl, 8);
    sl += __shfl_xor_sync(0xffffffffu, sl, 4);
    sl += __shfl_xor_sync(0xffffffffu, sl, 2);
    sl += __shfl_xor_sync(0xffffffffu, sl, 1);

    int g = batch[v];
    if ((unsigned)g < (unsigned)MAXG) {
        atomic_add_v4((float4*)(g_pooled + g * HD) + l, h);
        if (l == 0) atomicAdd(&g_counts[g], 1.0f);
    }
    if (l == 0) out[v] = sl + ba[0];
}

// ---- value head ----
__global__ void k_value(const float* __restrict__ Wc, const float* __restrict__ bc,
                        float* __restrict__ out, int n) {
    int g = blockIdx.x, lane = threadIdx.x;
    float s = g_pooled[g * HD + lane] * Wc[lane]
            + g_pooled[g * HD + 32 + lane] * Wc[32 + lane];
    s += __shfl_xor_sync(0xffffffffu, s, 16);
    s += __shfl_xor_sync(0xffffffffu, s, 8);
    s += __shfl_xor_sync(0xffffffffu, s, 4);
    s += __shfl_xor_sync(0xffffffffu, s, 2);
    s += __shfl_xor_sync(0xffffffffu, s, 1);
    if (lane == 0)
        out[n + g] = s / fmaxf(g_counts[g], 1.0f) + bc[0];
}

extern "C" void kernel_launch(void* const* d_in, const int* in_sizes, int n_in,
                              void* d_out, int out_size) {
    const float* x     = (const float*)d_in[0];
    const int*   ei    = (const int*)d_in[1];      // int32 (JAX x64 disabled)
    const int*   batch = (const int*)d_in[2];      // int32
    const float* W1    = (const float*)d_in[3];
    const float* b1    = (const float*)d_in[4];
    const float* W2    = (const float*)d_in[5];
    const float* b2    = (const float*)d_in[6];
    const float* Wa    = (const float*)d_in[7];
    const float* ba    = (const float*)d_in[8];
    const float* Wc    = (const float*)d_in[9];
    const float* bc    = (const float*)d_in[10];
    float* out = (float*)d_out;

    int n = in_sizes[2];
    int E = in_sizes[1] / 2;
    int G = out_size - n;   // = 64
    int nb = (n + SCB - 1) / SCB;

    int smem1 = 2 * HD * (128 + 4) * sizeof(float);   // 67584 (GEMM1)
    int smemF = 2 * HD * (64 + 4) * sizeof(float);    // 34816 (fuse1)
    cudaFuncSetAttribute(k_gemm1, cudaFuncAttributeMaxDynamicSharedMemorySize, smem1);
    cudaFuncSetAttribute(k_fuse1, cudaFuncAttributeMaxDynamicSharedMemorySize, smemF);

    // ---- fork: GEMM1 on side stream, CSR build on main stream ----
    cudaStream_t s1;
    cudaStreamCreateWithFlags(&s1, cudaStreamNonBlocking);
    cudaEvent_t ev_fork, ev_join;
    cudaEventCreateWithFlags(&ev_fork, cudaEventDisableTiming);
    cudaEventCreateWithFlags(&ev_join, cudaEventDisableTiming);

    cudaEventRecord(ev_fork, 0);
    cudaStreamWaitEvent(s1, ev_fork, 0);
    k_gemm1<<<(n + 63) / 64, 256, smem1, s1>>>(x, W1, n);
    cudaEventRecord(ev_join, s1);

    k_zero<<<(n + 255) / 256, 256>>>(n);
    k_hist<<<(E + 255) / 256, 256>>>(ei, E, n);
    k_scan1<<<nb, SCB>>>(n);
    k_scanB<<<(n + 255) / 256, 256>>>(n, nb);
    k_fill<<<(E + 255) / 256, 256>>>(ei, E, n);

    cudaStreamWaitEvent(0, ev_join, 0);   // join GEMM1

    k_fuse1<<<(n + 63) / 64, 256, smemF>>>(W2, b1, n);
    k_fuse2<<<(n * 16 + 255) / 256, 256>>>(b2, batch, Wa, ba, out, n);
    if (G > 0) k_value<<<G, 32>>>(Wc, bc, out, n);

    cudaEventDestroy(ev_fork);
    cudaEventDestroy(ev_join);
    cudaStreamDestroy(s1);
}

// round 16
// speedup vs baseline: 1.1112x; 1.0395x over previous
#include <cuda_runtime.h>
#include <cuda_fp16.h>

// GNNPolicy: 2-layer GCN + node logits head + graph mean-pool value head.
// CSR-gather aggregation with fp16 feature tables (fp32 accumulation),
// smem-staged GEMMs with f32x2 FMA, stream-forked GEMM1 || CSR build,
// gather1+GEMM2 fused, gather2+heads fused.
// Inputs: x[N,128] f32, edge_index[2,E] int32, batch[N] int32,
//   W1[128,64], b1[64], W2[64,64], b2[64], Wa[64,1], ba[1], Wc[64,1], bc[1]
// Output: concat(action_logits[N], value[G]) as float32, out_size = N + G.

#define HD 64
#define MAXN 100000
#define MAXE 1600000
#define MAXG 64
#define SCB  1024   // scan block width

typedef unsigned long long u64;

// ---- scratch ----
__device__ __align__(16) int     g_cnt[MAXN];
__device__ __align__(16) int     g_rowptr[MAXN];
__device__ __align__(16) int     g_cursor[MAXN];
__device__ __align__(16) int     g_csrc[MAXE];
__device__ __align__(16) int     g_bsum[256];
__device__ __align__(16) float   g_dinv[MAXN];
__device__ __align__(16) __half2 g_T [(size_t)MAXN * 32];  // layer1: raw X@W1 (fp16)
__device__ __align__(16) __half2 g_T2[(size_t)MAXN * 32];  // layer2: premult dinv (fp16)
__device__ __align__(16) float   g_pooled[MAXG * HD];
__device__ __align__(16) float   g_counts[MAXG];

// ---- packed f32x2 helpers ----
__device__ __forceinline__ u64 pk2(float a, float b) {
    u64 r; asm("mov.b64 %0, {%1, %2};" : "=l"(r) : "f"(a), "f"(b)); return r;
}
__device__ __forceinline__ void fma2(u64& d, u64 a, u64 b) {
    asm("fma.rn.f32x2 %0, %1, %2, %0;" : "+l"(d) : "l"(a), "l"(b));
}
__device__ __forceinline__ float hsum2(u64 v) {
    float x, y; asm("mov.b64 {%0, %1}, %2;" : "=f"(x), "=f"(y) : "l"(v)); return x + y;
}

// load 4 consecutive halves (chunk l of a 64-half row) as float4
__device__ __forceinline__ float4 ldh4(const __half2* row, int l) {
    uint2 q = ((const uint2*)row)[l];
    float2 f0 = __half22float2(*(__half2*)&q.x);
    float2 f1 = __half22float2(*(__half2*)&q.y);
    return make_float4(f0.x, f0.y, f1.x, f1.y);
}

__device__ __forceinline__ void atomic_add_v4(float4* addr, float4 v) {
#if defined(__CUDA_ARCH__) && (__CUDA_ARCH__ >= 900)
    atomicAdd(addr, v);
#else
    float* a = (float*)addr;
    atomicAdd(a + 0, v.x); atomicAdd(a + 1, v.y);
    atomicAdd(a + 2, v.z); atomicAdd(a + 3, v.w);
#endif
}

// ---- zero ----
__global__ void k_zero(int n) {
    int i = blockIdx.x * blockDim.x + threadIdx.x;
    if (i < n) g_cnt[i] = 0;
    if (i < MAXG * HD) g_pooled[i] = 0.0f;
    if (i < MAXG) g_counts[i] = 0.0f;
}

// ---- histogram over dst ----
__global__ void k_hist(const int* __restrict__ ei, int E, int n) {
    int e = blockIdx.x * blockDim.x + threadIdx.x;
    if (e < E) {
        int dst = ei[E + e];
        if ((unsigned)dst < (unsigned)n) atomicAdd(&g_cnt[dst], 1);
    }
}

// ---- scan level 1 ----
__global__ void k_scan1(int n) {
    __shared__ int s[SCB];
    int t = threadIdx.x;
    int i = blockIdx.x * SCB + t;
    int v = (i < n) ? g_cnt[i] : 0;
    s[t] = v;
    __syncthreads();
#pragma unroll
    for (int off = 1; off < SCB; off <<= 1) {
        int x = (t >= off) ? s[t - off] : 0;
        __syncthreads();
        s[t] += x;
        __syncthreads();
    }
    if (i < n) g_rowptr[i] = s[t] - v;
    if (t == SCB - 1) g_bsum[blockIdx.x] = s[t];
}

// ---- scanB: redundant block-sum scan + apply + cursors + dinv ----
__global__ void k_scanB(int n, int nb) {
    __shared__ int s[256];
    __shared__ int off[256];
    int t = threadIdx.x;
    int v = (t < nb) ? g_bsum[t] : 0;
    s[t] = v;
    __syncthreads();
#pragma unroll
    for (int o = 1; o < 256; o <<= 1) {
        int x = (t >= o) ? s[t - o] : 0;
        __syncthreads();
        s[t] += x;
        __syncthreads();
    }
    off[t] = s[t] - v;
    __syncthreads();
    int i = blockIdx.x * 256 + t;
    if (i < n) {
        int rp = g_rowptr[i] + off[i >> 10];
        g_rowptr[i] = rp;
        g_cursor[i] = rp;
        g_dinv[i]   = rsqrtf((float)(g_cnt[i] + 1));
    }
}

// ---- fill CSR ----
__global__ void k_fill(const int* __restrict__ ei, int E, int n) {
    int e = blockIdx.x * blockDim.x + threadIdx.x;
    if (e < E) {
        int src = ei[e];
        int dst = ei[E + e];
        if ((unsigned)src < (unsigned)n && (unsigned)dst < (unsigned)n) {
            int pos = atomicAdd(&g_cursor[dst], 1);
            g_csrc[pos] = src;
        }
    }
}

// ---- GEMM1: T = X @ W1 (raw; fp16 out; concurrent with CSR build) ----
__global__ void k_gemm1(const float* __restrict__ X, const float* __restrict__ W,
                        int n) {
    const int K = 128;
    extern __shared__ __align__(16) float sm[];
    float* Wt = sm;                       // [64][132]
    float* Xs = sm + HD * (K + 4);        // [64][132]
    const int NF4 = K / 4;

    int tid = threadIdx.x;
    int row0 = blockIdx.x * 64;

    for (int idx = tid; idx < K * HD; idx += 256) {
        int k = idx >> 6, c = idx & 63;
        Wt[c * (K + 4) + k] = W[idx];
    }
    for (int i = tid; i < 64 * NF4; i += 256) {
        int r = i / NF4, c = i % NF4;
        int rr = row0 + r;
        float4 v = make_float4(0.f, 0.f, 0.f, 0.f);
        if (rr < n) v = ((const float4*)X)[(size_t)rr * NF4 + c];
        *(float4*)&Xs[r * (K + 4) + c * 4] = v;
    }
    __syncthreads();

    int warp = tid >> 5, lane = tid & 31;
    const float* wt0 = &Wt[lane * (K + 4)];
    const float* wt1 = &Wt[(lane + 32) * (K + 4)];
    const float* xr0 = &Xs[(warp * 8) * (K + 4)];

    u64 acc0[8], acc1[8];
#pragma unroll
    for (int r = 0; r < 8; r++) { acc0[r] = 0ull; acc1[r] = 0ull; }

#pragma unroll 4
    for (int k = 0; k < K; k += 4) {
        float4 wa = *(const float4*)(wt0 + k);
        float4 wb = *(const float4*)(wt1 + k);
        u64 wa01 = pk2(wa.x, wa.y), wa23 = pk2(wa.z, wa.w);
        u64 wb01 = pk2(wb.x, wb.y), wb23 = pk2(wb.z, wb.w);
#pragma unroll
        for (int r = 0; r < 8; r++) {
            float4 xv = *(const float4*)(xr0 + r * (K + 4) + k);
            u64 x01 = pk2(xv.x, xv.y), x23 = pk2(xv.z, xv.w);
            fma2(acc0[r], x01, wa01); fma2(acc0[r], x23, wa23);
            fma2(acc1[r], x01, wb01); fma2(acc1[r], x23, wb23);
        }
    }

    int rbase = row0 + warp * 8;
#pragma unroll
    for (int r = 0; r < 8; r++) {
        int rr = rbase + r;
        float a0 = hsum2(acc0[r]);                 // col lane
        float a1 = hsum2(acc1[r]);                 // col lane+32
        float n0 = __shfl_down_sync(0xffffffffu, a0, 1);   // col lane+1
        float n1 = __shfl_down_sync(0xffffffffu, a1, 1);   // col lane+33
        if (((lane & 1) == 0) && rr < n) {
            __half2* row = g_T + (size_t)rr * 32;
            row[(lane >> 1)]      = __floats2half2_rn(a0, n0);
            row[16 + (lane >> 1)] = __floats2half2_rn(a1, n1);
        }
    }
}

// ---- fused gather1 + GEMM2 (agg1 in fp32 smem); fp16 table loads ----
__global__ void k_fuse1(const float* __restrict__ W2, const float* __restrict__ b1,
                        int n) {
    const int K = 64;
    extern __shared__ __align__(16) float sm[];
    float* Wt = sm;                       // [64][68]
    float* Xs = sm + HD * (K + 4);        // [64][68]

    int tid = threadIdx.x;
    int row0 = blockIdx.x * 64;

    for (int idx = tid; idx < K * HD; idx += 256) {
        int k = idx >> 6, c = idx & 63;
        Wt[c * (K + 4) + k] = W2[idx];
    }

    // gather phase: 16 lanes/node, 16 nodes in flight, 4 passes
    int l = tid & 15;
    float4 bb = ((const float4*)b1)[l];
#pragma unroll
    for (int it = 0; it < 4; it++) {
        int r = it * 16 + (tid >> 4);
        int v = row0 + r;
        float4 s = make_float4(0.f, 0.f, 0.f, 0.f);
        if (v < n) {
            float dv = g_dinv[v];
            float4 t = ldh4(g_T + (size_t)v * 32, l);
            s.x = t.x * dv; s.y = t.y * dv; s.z = t.z * dv; s.w = t.w * dv;
            int start = g_rowptr[v];
            int cnt   = g_cnt[v];
            int u = (cnt > 0) ? g_csrc[start] : 0;
            for (int j = 0; j < cnt; j++) {
                int un = (j + 1 < cnt) ? g_csrc[start + j + 1] : 0;
                float du = g_dinv[u];
                float4 tu = ldh4(g_T + (size_t)u * 32, l);
                s.x += tu.x * du; s.y += tu.y * du;
                s.z += tu.z * du; s.w += tu.w * du;
                u = un;
            }
            s.x = fmaxf(dv * s.x + bb.x, 0.0f);
            s.y = fmaxf(dv * s.y + bb.y, 0.0f);
            s.z = fmaxf(dv * s.z + bb.z, 0.0f);
            s.w = fmaxf(dv * s.w + bb.w, 0.0f);
        }
        *(float4*)&Xs[r * (K + 4) + l * 4] = s;
    }
    __syncthreads();

    // GEMM phase (packed f32x2)
    int warp = tid >> 5, lane = tid & 31;
    const float* wt0 = &Wt[lane * (K + 4)];
    const float* wt1 = &Wt[(lane + 32) * (K + 4)];
    const float* xr0 = &Xs[(warp * 8) * (K + 4)];

    u64 acc0[8], acc1[8];
#pragma unroll
    for (int r = 0; r < 8; r++) { acc0[r] = 0ull; acc1[r] = 0ull; }

#pragma unroll 4
    for (int k = 0; k < K; k += 4) {
        float4 wa = *(const float4*)(wt0 + k);
        float4 wb = *(const float4*)(wt1 + k);
        u64 wa01 = pk2(wa.x, wa.y), wa23 = pk2(wa.z, wa.w);
        u64 wb01 = pk2(wb.x, wb.y), wb23 = pk2(wb.z, wb.w);
#pragma unroll
        for (int r = 0; r < 8; r++) {
            float4 xv = *(const float4*)(xr0 + r * (K + 4) + k);
            u64 x01 = pk2(xv.x, xv.y), x23 = pk2(xv.z, xv.w);
            fma2(acc0[r], x01, wa01); fma2(acc0[r], x23, wa23);
            fma2(acc1[r], x01, wb01); fma2(acc1[r], x23, wb23);
        }
    }

    int rbase = row0 + warp * 8;
#pragma unroll
    for (int r = 0; r < 8; r++) {
        int rr = rbase + r;
        float di = (rr < n) ? g_dinv[rr] : 0.0f;
        float a0 = hsum2(acc0[r]) * di;            // col lane (premult dinv)
        float a1 = hsum2(acc1[r]) * di;            // col lane+32
        float n0 = __shfl_down_sync(0xffffffffu, a0, 1);
        float n1 = __shfl_down_sync(0xffffffffu, a1, 1);
        if (((lane & 1) == 0) && rr < n) {
            __half2* row = g_T2 + (size_t)rr * 32;
            row[(lane >> 1)]      = __floats2half2_rn(a0, n0);
            row[16 + (lane >> 1)] = __floats2half2_rn(a1, n1);
        }
    }
}

// ---- fused gather2 + heads (serial-prefetch gather; fp16 table loads) ----
__global__ void k_fuse2(const float* __restrict__ b2, const int* __restrict__ batch,
                        const float* __restrict__ Wa, const float* __restrict__ ba,
                        float* __restrict__ out, int n) {
    int tid = blockIdx.x * blockDim.x + threadIdx.x;
    int v = tid >> 4;
    if (v >= n) return;
    int l = tid & 15;
    int start = g_rowptr[v];
    int cnt   = g_cnt[v];
    float4 s = ldh4(g_T2 + (size_t)v * 32, l);     // self (premult dinv)
    int u = (cnt > 0) ? g_csrc[start] : 0;
    for (int j = 0; j < cnt; j++) {
        int un = (j + 1 < cnt) ? g_csrc[start + j + 1] : 0;
        float4 t = ldh4(g_T2 + (size_t)u * 32, l);
        s.x += t.x; s.y += t.y; s.z += t.z; s.w += t.w;
        u = un;
    }
    float dv = g_dinv[v];
    float4 bb = ((const float4*)b2)[l];
    float4 h;
    h.x = fmaxf(bb.x + dv * s.x, 0.0f);
    h.y = fmaxf(bb.y + dv * s.y, 0.0f);
    h.z = fmaxf(bb.z + dv * s.z, 0.0f);
    h.w = fmaxf(bb.w + dv * s.w, 0.0f);

    float4 wa = ((const float4*)Wa)[l];
    float sl = h.x * wa.x + h.y * wa.y + h.z * wa.z + h.w * wa.w;
    sl += __shfl_xor_sync(0xffffffffu, sl, 8);
    sl += __shfl_xor_sync(0xffffffffu, sl, 4);
    sl += __shfl_xor_sync(0xffffffffu, sl, 2);
    sl += __shfl_xor_sync(0xffffffffu, sl, 1);

    int g = batch[v];
    if ((unsigned)g < (unsigned)MAXG) {
        atomic_add_v4((float4*)(g_pooled + g * HD) + l, h);
        if (l == 0) atomicAdd(&g_counts[g], 1.0f);
    }
    if (l == 0) out[v] = sl + ba[0];
}

// ---- value head ----
__global__ void k_value(const float* __restrict__ Wc, const float* __restrict__ bc,
                        float* __restrict__ out, int n) {
    int g = blockIdx.x, lane = threadIdx.x;
    float s = g_pooled[g * HD + lane] * Wc[lane]
            + g_pooled[g * HD + 32 + lane] * Wc[32 + lane];
    s += __shfl_xor_sync(0xffffffffu, s, 16);
    s += __shfl_xor_sync(0xffffffffu, s, 8);
    s += __shfl_xor_sync(0xffffffffu, s, 4);
    s += __shfl_xor_sync(0xffffffffu, s, 2);
    s += __shfl_xor_sync(0xffffffffu, s, 1);
    if (lane == 0)
        out[n + g] = s / fmaxf(g_counts[g], 1.0f) + bc[0];
}

extern "C" void kernel_launch(void* const* d_in, const int* in_sizes, int n_in,
                              void* d_out, int out_size) {
    const float* x     = (const float*)d_in[0];
    const int*   ei    = (const int*)d_in[1];      // int32 (JAX x64 disabled)
    const int*   batch = (const int*)d_in[2];      // int32
    const float* W1    = (const float*)d_in[3];
    const float* b1    = (const float*)d_in[4];
    const float* W2    = (const float*)d_in[5];
    const float* b2    = (const float*)d_in[6];
    const float* Wa    = (const float*)d_in[7];
    const float* ba    = (const float*)d_in[8];
    const float* Wc    = (const float*)d_in[9];
    const float* bc    = (const float*)d_in[10];
    float* out = (float*)d_out;

    int n = in_sizes[2];
    int E = in_sizes[1] / 2;
    int G = out_size - n;   // = 64
    int nb = (n + SCB - 1) / SCB;

    int smem1 = 2 * HD * (128 + 4) * sizeof(float);   // 67584 (GEMM1)
    int smemF = 2 * HD * (64 + 4) * sizeof(float);    // 34816 (fuse1)
    cudaFuncSetAttribute(k_gemm1, cudaFuncAttributeMaxDynamicSharedMemorySize, smem1);
    cudaFuncSetAttribute(k_fuse1, cudaFuncAttributeMaxDynamicSharedMemorySize, smemF);

    // ---- fork: GEMM1 on side stream, CSR build on main stream ----
    cudaStream_t s1;
    cudaStreamCreateWithFlags(&s1, cudaStreamNonBlocking);
    cudaEvent_t ev_fork, ev_join;
    cudaEventCreateWithFlags(&ev_fork, cudaEventDisableTiming);
    cudaEventCreateWithFlags(&ev_join, cudaEventDisableTiming);

    cudaEventRecord(ev_fork, 0);
    cudaStreamWaitEvent(s1, ev_fork, 0);
    k_gemm1<<<(n + 63) / 64, 256, smem1, s1>>>(x, W1, n);
    cudaEventRecord(ev_join, s1);

    k_zero<<<(n + 255) / 256, 256>>>(n);
    k_hist<<<(E + 255) / 256, 256>>>(ei, E, n);
    k_scan1<<<nb, SCB>>>(n);
    k_scanB<<<(n + 255) / 256, 256>>>(n, nb);
    k_fill<<<(E + 255) / 256, 256>>>(ei, E, n);

    cudaStreamWaitEvent(0, ev_join, 0);   // join GEMM1

    k_fuse1<<<(n + 63) / 64, 256, smemF>>>(W2, b1, n);
    k_fuse2<<<(n * 16 + 255) / 256, 256>>>(b2, batch, Wa, ba, out, n);
    if (G > 0) k_value<<<G, 32>>>(Wc, bc, out, n);

    cudaEventDestroy(ev_fork);
    cudaEventDestroy(ev_join);
    cudaStreamDestroy(s1);
}